// round 15
// baseline (speedup 1.0000x reference)
#include <cuda_runtime.h>
#include <cuda_fp16.h>
#include <cstdint>

#define N_NODES 8192
#define IN_F    512
#define OUT_F   128
#define ALPHA   0.2f
#define BN_EPS  1e-5f

// ---------------- scratch ----------------
__device__ __align__(16) __half g_ham16T[OUT_F * IN_F];      // [c][k] fp16, 128x512
__device__ __align__(16) float  g_h[N_NODES * OUT_F];        // fp32 (staging for s1/s2 path)
__device__ __align__(16) __half g_hT16[OUT_F * N_NODES];     // fp16 transposed [c][j]
__device__ __align__(16) float  g_hp0[N_NODES * OUT_F];      // partial, j-half 0
__device__ __align__(16) float  g_hp1[N_NODES * OUT_F];      // partial, j-half 1
__device__ float  g_z0[N_NODES];
__device__ float  g_z1[N_NODES];
__device__ float  g_s1[N_NODES];
__device__ float  g_s2[N_NODES];
__device__ unsigned int g_s2max_u = 0x007FFFFFu;             // encoded -inf (idempotent)
__device__ __align__(16) float2   g_A12[N_NODES];            // fp32 {A1, A2}
__device__ __align__(8)  uint32_t g_E12h[N_NODES];           // half2 {E1, E2}, both <= 1
__device__ float g_colsum[OUT_F];
__device__ float g_colsumsq[OUT_F];

// ---------------- helpers ----------------
__device__ __forceinline__ uint32_t smem_u32(const void* p) {
    uint32_t a;
    asm("{ .reg .u64 t; cvta.to.shared.u64 t, %1; cvt.u32.u64 %0, t; }" : "=r"(a) : "l"(p));
    return a;
}
__device__ __forceinline__ void cp16(uint32_t dst, const void* src) {
    asm volatile("cp.async.cg.shared.global [%0], [%1], 16;" :: "r"(dst), "l"(src) : "memory");
}
__device__ __forceinline__ void cp_commit() {
    asm volatile("cp.async.commit_group;" ::: "memory");
}
__device__ __forceinline__ void cp_wait0() {
    asm volatile("cp.async.wait_group 0;" ::: "memory");
}
__device__ __forceinline__ void cp_wait1() {
    asm volatile("cp.async.wait_group 1;" ::: "memory");
}
__device__ __forceinline__ void ldsm4(uint32_t* r, uint32_t addr) {
    asm volatile("ldmatrix.sync.aligned.m8n8.x4.shared.b16 {%0,%1,%2,%3}, [%4];"
                 : "=r"(r[0]), "=r"(r[1]), "=r"(r[2]), "=r"(r[3]) : "r"(addr));
}
__device__ __forceinline__ void mma16(float* c, const uint32_t* a, const uint32_t* b) {
    asm volatile(
        "mma.sync.aligned.m16n8k16.row.col.f32.f16.f16.f32 "
        "{%0,%1,%2,%3}, {%4,%5,%6,%7}, {%8,%9}, {%0,%1,%2,%3};"
        : "+f"(c[0]), "+f"(c[1]), "+f"(c[2]), "+f"(c[3])
        : "r"(a[0]), "r"(a[1]), "r"(a[2]), "r"(a[3]), "r"(b[0]), "r"(b[1]));
}
__device__ __forceinline__ float quat_sign(int rb, int cb) {
    float sgn = 1.f;
    if (cb == 0) { if (rb != 0) sgn = -1.f; }
    else if (rb == (cb % 3) + 1) sgn = -1.f;
    return sgn;
}

// ---------------- K0: transposed fp16 hamilton [c][k] ----------------
__global__ void k_ham16(const float* __restrict__ W) {
    int idx = blockIdx.x * blockDim.x + threadIdx.x;   // 0..65535
    int c = idx >> 9, k = idx & 511;
    int rb = k >> 7, rr = k & 127;
    int cb = c >> 5, cc = c & 31;
    int comp = rb ^ cb;
    g_ham16T[idx] = __float2half(quat_sign(rb, cb) * W[rr * 128 + comp * 32 + cc]);
}

// ---------------- K1: h = input @ hamilton via fp16 mma, pipelined ----------------
#define KH_AB 9216                         // 64 rows * 144 B
#define KH_BB 18432                        // 128 rows * 144 B
#define KH_SMEM (2 * KH_AB + 3 * KH_BB)    // 73728
__global__ void __launch_bounds__(256) k_h(const float* __restrict__ inp,
                                           const float* __restrict__ a_vec) {
    extern __shared__ __align__(16) char smh[];
    const uint32_t sb = smem_u32(smh);
    const uint32_t B0 = sb + 2 * KH_AB;

    const int tid  = threadIdx.x;
    const int wid  = tid >> 5;
    const int lane = tid & 31;
    const int gid  = lane >> 2;
    const int t4   = lane & 3;
    const int i0   = blockIdx.x * 64;
    const int m0   = (wid >> 2) * 32;
    const int n0   = (wid & 3) * 32;

    const uint32_t aoffr = (uint32_t)((m0 + (lane & 7) + ((lane >> 3) & 1) * 8) * 144
                                      + ((lane >> 4) & 1) * 16);
    const uint32_t boffr = (uint32_t)((n0 + (lane & 7) + ((lane >> 4) & 1) * 8) * 144
                                      + ((lane >> 3) & 1) * 16);

    const int arow = tid >> 2;            // 0..63
    const int akq  = (tid & 3) * 16;      // 0/16/32/48
    const float* asrc = inp + (size_t)(i0 + arow) * IN_F + akq;

    float acc[2][4][4];
#pragma unroll
    for (int mb = 0; mb < 2; mb++)
#pragma unroll
        for (int nb = 0; nb < 4; nb++)
#pragma unroll
            for (int q = 0; q < 4; q++) acc[mb][nb][q] = 0.f;

#pragma unroll
    for (int s = 0; s < 2; s++) {
        uint32_t bdst = B0 + (uint32_t)s * KH_BB;
        const __half* src = g_ham16T + s * 64;
#pragma unroll
        for (int q = 0; q < 4; q++) {
            int idx = q * 256 + tid;
            int c = idx >> 3, f8 = idx & 7;
            cp16(bdst + (uint32_t)(c * 144 + f8 * 16), src + c * IN_F + f8 * 8);
        }
        cp_commit();
    }
    float4 av4[4];
#pragma unroll
    for (int g = 0; g < 4; g++) av4[g] = *(const float4*)(asrc + g * 4);

    for (int cc = 0; cc < 8; cc++) {
        const int p = cc & 1;
        const int b3 = cc - (cc / 3) * 3;          // cc % 3

        {
            __half2 h0 = __floats2half2_rn(av4[0].x, av4[0].y);
            __half2 h1 = __floats2half2_rn(av4[0].z, av4[0].w);
            __half2 h2 = __floats2half2_rn(av4[1].x, av4[1].y);
            __half2 h3 = __floats2half2_rn(av4[1].z, av4[1].w);
            __half2 h4 = __floats2half2_rn(av4[2].x, av4[2].y);
            __half2 h5 = __floats2half2_rn(av4[2].z, av4[2].w);
            __half2 h6 = __floats2half2_rn(av4[3].x, av4[3].y);
            __half2 h7 = __floats2half2_rn(av4[3].z, av4[3].w);
            uint4 s0 = { *(uint32_t*)&h0, *(uint32_t*)&h1, *(uint32_t*)&h2, *(uint32_t*)&h3 };
            uint4 s1 = { *(uint32_t*)&h4, *(uint32_t*)&h5, *(uint32_t*)&h6, *(uint32_t*)&h7 };
            *(uint4*)(smh + p * KH_AB + arow * 144 + akq * 2)      = s0;
            *(uint4*)(smh + p * KH_AB + arow * 144 + akq * 2 + 16) = s1;
        }
        if (cc < 7) {
#pragma unroll
            for (int g = 0; g < 4; g++) av4[g] = *(const float4*)(asrc + (cc + 1) * 64 + g * 4);
        }

        if (cc < 7) cp_wait1(); else cp_wait0();
        __syncthreads();

        if (cc + 2 < 8) {
            const int b32 = (cc + 2) - ((cc + 2) / 3) * 3;
            uint32_t bdst = B0 + (uint32_t)b32 * KH_BB;
            const __half* src = g_ham16T + (cc + 2) * 64;
#pragma unroll
            for (int q = 0; q < 4; q++) {
                int idx = q * 256 + tid;
                int c = idx >> 3, f8 = idx & 7;
                cp16(bdst + (uint32_t)(c * 144 + f8 * 16), src + c * IN_F + f8 * 8);
            }
            cp_commit();
        }

        {
            const uint32_t pa = sb + (uint32_t)p * KH_AB + aoffr;
            const uint32_t pb = B0 + (uint32_t)b3 * KH_BB + boffr;
#pragma unroll
            for (int ks = 0; ks < 4; ks++) {
                uint32_t a0[4], a1[4], b01[4], b23[4];
                ldsm4(a0, pa + ks * 32);
                ldsm4(a1, pa + ks * 32 + 16 * 144);
                ldsm4(b01, pb + ks * 32);
                ldsm4(b23, pb + ks * 32 + 16 * 144);
                mma16(acc[0][0], a0, b01 + 0);
                mma16(acc[0][1], a0, b01 + 2);
                mma16(acc[0][2], a0, b23 + 0);
                mma16(acc[0][3], a0, b23 + 2);
                mma16(acc[1][0], a1, b01 + 0);
                mma16(acc[1][1], a1, b01 + 2);
                mma16(acc[1][2], a1, b23 + 0);
                mma16(acc[1][3], a1, b23 + 2);
            }
        }
    }
    __syncthreads();

    float* C = (float*)smh;                // 64 x 132 floats = 33792 B
#pragma unroll
    for (int mb = 0; mb < 2; mb++) {
        int r0 = m0 + mb * 16 + gid;
#pragma unroll
        for (int nb = 0; nb < 4; nb++) {
            int col = n0 + nb * 8 + t4 * 2;
            *(float2*)(C + r0 * 132 + col)       = make_float2(acc[mb][nb][0], acc[mb][nb][1]);
            *(float2*)(C + (r0 + 8) * 132 + col) = make_float2(acc[mb][nb][2], acc[mb][nb][3]);
        }
    }
    __syncthreads();

    {
        int r = tid >> 2, cq = (tid & 3) * 32;
#pragma unroll
        for (int q = 0; q < 8; q++) {
            float4 v = *(float4*)(C + r * 132 + cq + q * 4);
            *(float4*)(g_h + (size_t)(i0 + r) * OUT_F + cq + q * 4) = v;
        }
    }
    {
        int c = tid >> 1, j0 = (tid & 1) * 32;
        uint32_t hw[16];
#pragma unroll
        for (int q = 0; q < 16; q++) {
            float f0 = C[(j0 + 2 * q) * 132 + c];
            float f1 = C[(j0 + 2 * q + 1) * 132 + c];
            __half2 h = __floats2half2_rn(f0, f1);
            hw[q] = *(uint32_t*)&h;
        }
        uint4* dst = (uint4*)(g_hT16 + (size_t)c * N_NODES + i0 + j0);
#pragma unroll
        for (int q = 0; q < 4; q++)
            dst[q] = make_uint4(hw[q * 4], hw[q * 4 + 1], hw[q * 4 + 2], hw[q * 4 + 3]);
    }
    {
        float a1v[4], a2v[4];
#pragma unroll
        for (int q = 0; q < 4; q++) {
            a1v[q] = a_vec[lane + q * 32];
            a2v[q] = a_vec[OUT_F + lane + q * 32];
        }
        float m2 = -1e30f;
#pragma unroll
        for (int rr = 0; rr < 8; rr++) {
            int r = wid * 8 + rr;
            float s1 = 0.f, s2 = 0.f;
#pragma unroll
            for (int q = 0; q < 4; q++) {
                float hv = C[r * 132 + lane + q * 32];
                s1 = fmaf(hv, a1v[q], s1);
                s2 = fmaf(hv, a2v[q], s2);
            }
#pragma unroll
            for (int off = 16; off > 0; off >>= 1) {
                s1 += __shfl_xor_sync(0xffffffffu, s1, off);
                s2 += __shfl_xor_sync(0xffffffffu, s2, off);
            }
            if (lane == 0) {
                g_s1[i0 + r] = s1;
                g_s2[i0 + r] = s2;
                m2 = fmaxf(m2, s2);
            }
        }
        if (lane == 0) {
            uint32_t u = __float_as_uint(m2);
            u = (u & 0x80000000u) ? ~u : (u | 0x80000000u);
            atomicMax(&g_s2max_u, u);
        }
    }
}

// ---------------- K2: per-node exp factors (rescaled so all <= 1), + zero BN sums ----------------
__global__ void k_prep() {
    int i = blockIdx.x * blockDim.x + threadIdx.x;
    if (blockIdx.x == 0 && threadIdx.x < 128) {
        g_colsum[threadIdx.x] = 0.f; g_colsumsq[threadIdx.x] = 0.f;
    }
    uint32_t mu = g_s2max_u;
    float s2max = (mu & 0x80000000u) ? __uint_as_float(mu ^ 0x80000000u)
                                     : __uint_as_float(~mu);
    float s1 = g_s1[i], s2 = g_s2[i];
    float t = s1 + s2max;
    float m = (t > 0.f) ? t : ALPHA * t;
    float A1 = __expf(s1 + s2max - m);
    float A2 = __expf(ALPHA * (s1 + s2max) - m);
    float E1 = __expf(s2 - s2max);
    float E2 = __expf(ALPHA * (s2 - s2max));
    g_A12[i] = make_float2(A1, A2);
    __half2 e = __floats2half2_rn(E1, E2);
    g_E12h[i] = *(uint32_t*)&e;
}

// ---------------- K3: fused attention (R14 skeleton; E12 via cp.async smem ring) ----------------
// 256 CTAs (128 rowblocks x 2 j-halves) x 256 thr. BM=64, BN=128, BK=64, 64 chunks.
#define PT_B 9216                         // 64 rows * 144 B
#define HS_B 18432                        // 128 rows * 144 B
#define H_OFF (2 * PT_B)                  // 18432
#define Z_OFF (H_OFF + 3 * HS_B)          // 73728
#define E_OFF (Z_OFF + 256)               // 73984; 3 x 256 B E ring
#define ATTN_SMEM (E_OFF + 768)           // 74752
__global__ void __launch_bounds__(256, 2) k_attn(const int* __restrict__ adj) {
    extern __shared__ __align__(16) char smem[];
    const uint32_t sb = smem_u32(smem);
    float* zsh = (float*)(smem + Z_OFF);

    const int tid  = threadIdx.x;
    const int wid  = tid >> 5;
    const int lane = tid & 31;
    const int gid  = lane >> 2;
    const int t4   = lane & 3;
    const int bid  = blockIdx.x;
    const int i0   = (bid >> 1) * 64;
    const int jb0  = (bid & 1) * 4096;
    const int m0   = (wid >> 2) * 32;
    const int n0   = (wid & 3) * 32;

    if (tid < 64) zsh[tid] = 0.f;

    const int prow = tid >> 2;
    const int jl0  = (tid & 3) * 16;
    const float2 a12 = g_A12[i0 + prow];
    const float A1 = a12.x, A2 = a12.y;
    const int* arow = adj + (size_t)(i0 + prow) * N_NODES + jb0 + jl0;

    const uint32_t aoffr = (uint32_t)((m0 + (lane & 7) + ((lane >> 3) & 1) * 8) * 144
                                      + ((lane >> 4) & 1) * 16);
    const uint32_t boffr = (uint32_t)((n0 + (lane & 7) + ((lane >> 4) & 1) * 8) * 144
                                      + ((lane >> 3) & 1) * 16);

    float acc[2][4][4];
#pragma unroll
    for (int mb = 0; mb < 2; mb++)
#pragma unroll
        for (int nb = 0; nb < 4; nb++)
#pragma unroll
            for (int q = 0; q < 4; q++) acc[mb][nb][q] = 0.f;
    float zacc = 0.f;

    // ---- prologue: G1 = {H(0), E(0..2)}, G2 = {H(1)}; wait G1; prefetch adj(0) ----
#pragma unroll
    for (int s = 0; s < 2; s++) {
        uint32_t hdst = sb + H_OFF + (uint32_t)s * HS_B;
        const __half* src = g_hT16 + jb0 + s * 64;
#pragma unroll
        for (int q = 0; q < 4; q++) {
            int idx = q * 256 + tid;
            int c = idx >> 3, f8 = idx & 7;
            cp16(hdst + (uint32_t)(c * 144 + f8 * 16),
                 src + (size_t)c * N_NODES + f8 * 8);
        }
        if (s == 0 && tid < 48)
            cp16(sb + E_OFF + tid * 16, g_E12h + jb0 + tid * 4);   // E(0..2)
        cp_commit();
    }
    cp_wait1();          // G1 done: E(0..2) + H(0) resident
    __syncthreads();

    int4 av[4];
#pragma unroll
    for (int g = 0; g < 4; g++) av[g] = *(const int4*)(arow + g * 4);

    for (int cc = 0; cc < 64; cc++) {
        const int p = cc & 1;
        const int hb = cc - (cc / 3) * 3;      // cc % 3

        // ---- build P(cc): adj from regs, E from smem ring (broadcast LDS) ----
        {
            char* PtB = smem + p * PT_B;
            const char* Eb = smem + E_OFF + hb * 256 + jl0 * 4;
            uint4 ew[4];
            ew[0] = *(const uint4*)(Eb);
            ew[1] = *(const uint4*)(Eb + 16);
            ew[2] = *(const uint4*)(Eb + 32);
            ew[3] = *(const uint4*)(Eb + 48);
#pragma unroll
            for (int g = 0; g < 4; g++) {
                int4 a = av[g];
                float2 f0 = __half22float2(*(__half2*)&ew[g].x);
                float2 f1 = __half22float2(*(__half2*)&ew[g].y);
                float2 f2 = __half22float2(*(__half2*)&ew[g].z);
                float2 f3 = __half22float2(*(__half2*)&ew[g].w);
                float q0 = fmaxf(A1 * f0.x, A2 * f0.y);
                float q1 = fmaxf(A1 * f1.x, A2 * f1.y);
                float q2 = fmaxf(A1 * f2.x, A2 * f2.y);
                float q3 = fmaxf(A1 * f3.x, A2 * f3.y);
                if (a.x <= 0) q0 = 0.f;
                if (a.y <= 0) q1 = 0.f;
                if (a.z <= 0) q2 = 0.f;
                if (a.w <= 0) q3 = 0.f;
                __half2 h20 = __floats2half2_rn(q0, q1);
                __half2 h21 = __floats2half2_rn(q2, q3);
                float2 r0 = __half22float2(h20);
                float2 r1 = __half22float2(h21);
                zacc += (r0.x + r0.y) + (r1.x + r1.y);
                uint2 st = { *(uint32_t*)&h20, *(uint32_t*)&h21 };
                *(uint2*)(PtB + prow * 144 + (jl0 + g * 4) * 2) = st;
            }
        }

        // ---- prefetch adj for cc+1 (in flight across MMA) ----
        if (cc < 63) {
            const int nj = (cc + 1) * 64;
#pragma unroll
            for (int g = 0; g < 4; g++) av[g] = *(const int4*)(arow + nj + g * 4);
        }

        if (cc < 62) cp_wait1(); else cp_wait0();
        __syncthreads();     // P(cc) visible; H(cc) resident; MMA(cc-1) complete

        // ---- stage H(cc+2) + E(cc+3) ----
        if (cc + 2 < 64) {
            const int hb2 = (cc + 2) - ((cc + 2) / 3) * 3;
            uint32_t hdst = sb + H_OFF + (uint32_t)hb2 * HS_B;
            const __half* src = g_hT16 + jb0 + (cc + 2) * 64;
#pragma unroll
            for (int q = 0; q < 4; q++) {
                int idx = q * 256 + tid;
                int c = idx >> 3, f8 = idx & 7;
                cp16(hdst + (uint32_t)(c * 144 + f8 * 16),
                     src + (size_t)c * N_NODES + f8 * 8);
            }
            if (cc + 3 < 64 && tid < 16)
                cp16(sb + E_OFF + (uint32_t)hb * 256 + tid * 16,     // (cc+3)%3 == cc%3
                     g_E12h + jb0 + (cc + 3) * 64 + tid * 4);
            cp_commit();
        }

        // ---- MMA(cc): A from Pbuf[p], B from Hbuf[hb] ----
        {
            const uint32_t pa = sb + (uint32_t)p * PT_B + aoffr;
            const uint32_t pb = sb + H_OFF + (uint32_t)hb * HS_B + boffr;
#pragma unroll
            for (int ks = 0; ks < 4; ks++) {
                uint32_t a0[4], a1[4], b01[4], b23[4];
                ldsm4(a0, pa + ks * 32);
                ldsm4(a1, pa + ks * 32 + 16 * 144);
                ldsm4(b01, pb + ks * 32);
                ldsm4(b23, pb + ks * 32 + 16 * 144);
                mma16(acc[0][0], a0, b01 + 0);
                mma16(acc[0][1], a0, b01 + 2);
                mma16(acc[0][2], a0, b23 + 0);
                mma16(acc[0][3], a0, b23 + 2);
                mma16(acc[1][0], a1, b01 + 0);
                mma16(acc[1][1], a1, b01 + 2);
                mma16(acc[1][2], a1, b23 + 0);
                mma16(acc[1][3], a1, b23 + 2);
            }
        }
    }

    // ---- epilogue: write UNnormalized partials + z ----
    atomicAdd(&zsh[prow], zacc);
    __syncthreads();
    float* hpD = (bid & 1) ? g_hp1 : g_hp0;
    float* zD  = (bid & 1) ? g_z1  : g_z0;
    if (tid < 64) zD[i0 + tid] = zsh[tid];
#pragma unroll
    for (int mb = 0; mb < 2; mb++) {
        int r0 = m0 + mb * 16 + gid;
#pragma unroll
        for (int nb = 0; nb < 4; nb++) {
            int col = n0 + nb * 8 + t4 * 2;
            float2 v0 = {acc[mb][nb][0], acc[mb][nb][1]};
            float2 v1 = {acc[mb][nb][2], acc[mb][nb][3]};
            *(float2*)(hpD + (size_t)(i0 + r0) * OUT_F + col)     = v0;
            *(float2*)(hpD + (size_t)(i0 + r0 + 8) * OUT_F + col) = v1;
        }
    }
}

// ---------------- K4: BN column stats directly from partials ----------------
__global__ void k_stats() {
    int col = threadIdx.x & 127;
    int h = threadIdx.x >> 7;
    int r0 = blockIdx.x * 32;
    float s = 0.f, q = 0.f;
    for (int r = h; r < 32; r += 2) {
        int row = r0 + r;
        size_t idx = (size_t)row * OUT_F + col;
        float z = g_z0[row] + g_z1[row];
        float m = (g_hp0[idx] + g_hp1[idx]) / z;
        s += m; q = fmaf(m, m, q);
    }
    atomicAdd(&g_colsum[col], s);
    atomicAdd(&g_colsumsq[col], q);
}

// ---------------- K5: merge + normalize + BatchNorm + ELU (float4) ----------------
__global__ void k_bn(const float* __restrict__ gamma, const float* __restrict__ beta,
                     float* __restrict__ out) {
    int t = blockIdx.x * blockDim.x + threadIdx.x;    // 0..262143
    int base = t * 4;
    int col = base & 127;
    int row = base >> 7;
    const float invN = 1.0f / (float)N_NODES;
    float4 cs = *(const float4*)(g_colsum + col);
    float4 cq = *(const float4*)(g_colsumsq + col);
    float4 gm = *(const float4*)(gamma + col);
    float4 bt = *(const float4*)(beta + col);
    float4 a = *(const float4*)(g_hp0 + base);
    float4 b = *(const float4*)(g_hp1 + base);
    float invz = 1.0f / (g_z0[row] + g_z1[row]);
    float4 o;
    {
        float mean = cs.x * invN;
        float var  = cq.x * invN - mean * mean;
        float v = ((a.x + b.x) * invz - mean) * rsqrtf(var + BN_EPS) * gm.x + bt.x;
        o.x = (v > 0.f) ? v : expm1f(v);
    }
    {
        float mean = cs.y * invN;
        float var  = cq.y * invN - mean * mean;
        float v = ((a.y + b.y) * invz - mean) * rsqrtf(var + BN_EPS) * gm.y + bt.y;
        o.y = (v > 0.f) ? v : expm1f(v);
    }
    {
        float mean = cs.z * invN;
        float var  = cq.z * invN - mean * mean;
        float v = ((a.z + b.z) * invz - mean) * rsqrtf(var + BN_EPS) * gm.z + bt.z;
        o.z = (v > 0.f) ? v : expm1f(v);
    }
    {
        float mean = cs.w * invN;
        float var  = cq.w * invN - mean * mean;
        float v = ((a.w + b.w) * invz - mean) * rsqrtf(var + BN_EPS) * gm.w + bt.w;
        o.w = (v > 0.f) ? v : expm1f(v);
    }
    *(float4*)(out + base) = o;
}

// ---------------- launch ----------------
extern "C" void kernel_launch(void* const* d_in, const int* in_sizes, int n_in,
                              void* d_out, int out_size) {
    (void)in_sizes; (void)n_in; (void)out_size;
    const float* inp   = (const float*)d_in[0];
    const int*   adj   = (const int*)  d_in[1];
    const float* W     = (const float*)d_in[2];
    const float* a_vec = (const float*)d_in[3];
    const float* gamma = (const float*)d_in[4];
    const float* beta  = (const float*)d_in[5];
    float* out = (float*)d_out;

    static int smem_set = 0;
    if (!smem_set) {
        cudaFuncSetAttribute(k_attn, cudaFuncAttributeMaxDynamicSharedMemorySize, ATTN_SMEM);
        cudaFuncSetAttribute(k_h,    cudaFuncAttributeMaxDynamicSharedMemorySize, KH_SMEM);
        smem_set = 1;
    }

    k_ham16<<<256, 256>>>(W);
    k_h    <<<128, 256, KH_SMEM>>>(inp, a_vec);
    k_prep <<<32, 256>>>();
    k_attn <<<256, 256, ATTN_SMEM>>>(adj);     // launch #4 -> ncu captures this
    k_stats<<<256, 256>>>();
    k_bn   <<<1024, 256>>>(gamma, beta, out);
}

// round 16
// speedup vs baseline: 1.2641x; 1.2641x over previous
#include <cuda_runtime.h>
#include <cuda_fp16.h>
#include <cstdint>

#define N_NODES 8192
#define IN_F    512
#define OUT_F   128
#define ALPHA   0.2f
#define BN_EPS  1e-5f

// ---------------- scratch ----------------
__device__ __align__(16) __half g_ham16T[OUT_F * IN_F];      // [c][k] fp16, 128x512
__device__ __align__(16) float  g_h[N_NODES * OUT_F];        // fp32 (staging for s1/s2 path)
__device__ __align__(16) __half g_hT16[OUT_F * N_NODES];     // fp16 transposed [c][j]
__device__ __align__(16) float  g_hp0[N_NODES * OUT_F];      // partial, j-half 0
__device__ __align__(16) float  g_hp1[N_NODES * OUT_F];      // partial, j-half 1
__device__ float  g_z0[N_NODES];
__device__ float  g_z1[N_NODES];
__device__ float  g_s1[N_NODES];
__device__ float  g_s2[N_NODES];
__device__ unsigned int g_s2max_u = 0x007FFFFFu;             // encoded -inf (idempotent)
__device__ __align__(16) float2   g_A12[N_NODES];            // fp32 {A1, A2}
__device__ __align__(8)  uint32_t g_E12h[N_NODES];           // half2 {E1, E2}, both <= 1
__device__ float g_colsum[OUT_F];
__device__ float g_colsumsq[OUT_F];

// ---------------- helpers ----------------
__device__ __forceinline__ uint32_t smem_u32(const void* p) {
    uint32_t a;
    asm("{ .reg .u64 t; cvta.to.shared.u64 t, %1; cvt.u32.u64 %0, t; }" : "=r"(a) : "l"(p));
    return a;
}
__device__ __forceinline__ void cp16(uint32_t dst, const void* src) {
    asm volatile("cp.async.cg.shared.global [%0], [%1], 16;" :: "r"(dst), "l"(src) : "memory");
}
__device__ __forceinline__ void cp_commit() {
    asm volatile("cp.async.commit_group;" ::: "memory");
}
__device__ __forceinline__ void cp_wait0() {
    asm volatile("cp.async.wait_group 0;" ::: "memory");
}
__device__ __forceinline__ void cp_wait1() {
    asm volatile("cp.async.wait_group 1;" ::: "memory");
}
__device__ __forceinline__ void ldsm4(uint32_t* r, uint32_t addr) {
    asm volatile("ldmatrix.sync.aligned.m8n8.x4.shared.b16 {%0,%1,%2,%3}, [%4];"
                 : "=r"(r[0]), "=r"(r[1]), "=r"(r[2]), "=r"(r[3]) : "r"(addr));
}
__device__ __forceinline__ void mma16(float* c, const uint32_t* a, const uint32_t* b) {
    asm volatile(
        "mma.sync.aligned.m16n8k16.row.col.f32.f16.f16.f32 "
        "{%0,%1,%2,%3}, {%4,%5,%6,%7}, {%8,%9}, {%0,%1,%2,%3};"
        : "+f"(c[0]), "+f"(c[1]), "+f"(c[2]), "+f"(c[3])
        : "r"(a[0]), "r"(a[1]), "r"(a[2]), "r"(a[3]), "r"(b[0]), "r"(b[1]));
}
__device__ __forceinline__ float quat_sign(int rb, int cb) {
    float sgn = 1.f;
    if (cb == 0) { if (rb != 0) sgn = -1.f; }
    else if (rb == (cb % 3) + 1) sgn = -1.f;
    return sgn;
}

// ---------------- K0: transposed fp16 hamilton [c][k] ----------------
__global__ void k_ham16(const float* __restrict__ W) {
    int idx = blockIdx.x * blockDim.x + threadIdx.x;   // 0..65535
    int c = idx >> 9, k = idx & 511;
    int rb = k >> 7, rr = k & 127;
    int cb = c >> 5, cc = c & 31;
    int comp = rb ^ cb;
    g_ham16T[idx] = __float2half(quat_sign(rb, cb) * W[rr * 128 + comp * 32 + cc]);
}

// ---------------- K1: h = input @ hamilton via fp16 mma, pipelined ----------------
#define KH_AB 9216                         // 64 rows * 144 B
#define KH_BB 18432                        // 128 rows * 144 B
#define KH_SMEM (2 * KH_AB + 3 * KH_BB)    // 73728
__global__ void __launch_bounds__(256) k_h(const float* __restrict__ inp,
                                           const float* __restrict__ a_vec) {
    extern __shared__ __align__(16) char smh[];
    const uint32_t sb = smem_u32(smh);
    const uint32_t B0 = sb + 2 * KH_AB;

    const int tid  = threadIdx.x;
    const int wid  = tid >> 5;
    const int lane = tid & 31;
    const int gid  = lane >> 2;
    const int t4   = lane & 3;
    const int i0   = blockIdx.x * 64;
    const int m0   = (wid >> 2) * 32;
    const int n0   = (wid & 3) * 32;

    const uint32_t aoffr = (uint32_t)((m0 + (lane & 7) + ((lane >> 3) & 1) * 8) * 144
                                      + ((lane >> 4) & 1) * 16);
    const uint32_t boffr = (uint32_t)((n0 + (lane & 7) + ((lane >> 4) & 1) * 8) * 144
                                      + ((lane >> 3) & 1) * 16);

    const int arow = tid >> 2;            // 0..63
    const int akq  = (tid & 3) * 16;      // 0/16/32/48
    const float* asrc = inp + (size_t)(i0 + arow) * IN_F + akq;

    float acc[2][4][4];
#pragma unroll
    for (int mb = 0; mb < 2; mb++)
#pragma unroll
        for (int nb = 0; nb < 4; nb++)
#pragma unroll
            for (int q = 0; q < 4; q++) acc[mb][nb][q] = 0.f;

#pragma unroll
    for (int s = 0; s < 2; s++) {
        uint32_t bdst = B0 + (uint32_t)s * KH_BB;
        const __half* src = g_ham16T + s * 64;
#pragma unroll
        for (int q = 0; q < 4; q++) {
            int idx = q * 256 + tid;
            int c = idx >> 3, f8 = idx & 7;
            cp16(bdst + (uint32_t)(c * 144 + f8 * 16), src + c * IN_F + f8 * 8);
        }
        cp_commit();
    }
    float4 av4[4];
#pragma unroll
    for (int g = 0; g < 4; g++) av4[g] = *(const float4*)(asrc + g * 4);

    for (int cc = 0; cc < 8; cc++) {
        const int p = cc & 1;
        const int b3 = cc - (cc / 3) * 3;          // cc % 3

        {
            __half2 h0 = __floats2half2_rn(av4[0].x, av4[0].y);
            __half2 h1 = __floats2half2_rn(av4[0].z, av4[0].w);
            __half2 h2 = __floats2half2_rn(av4[1].x, av4[1].y);
            __half2 h3 = __floats2half2_rn(av4[1].z, av4[1].w);
            __half2 h4 = __floats2half2_rn(av4[2].x, av4[2].y);
            __half2 h5 = __floats2half2_rn(av4[2].z, av4[2].w);
            __half2 h6 = __floats2half2_rn(av4[3].x, av4[3].y);
            __half2 h7 = __floats2half2_rn(av4[3].z, av4[3].w);
            uint4 s0 = { *(uint32_t*)&h0, *(uint32_t*)&h1, *(uint32_t*)&h2, *(uint32_t*)&h3 };
            uint4 s1 = { *(uint32_t*)&h4, *(uint32_t*)&h5, *(uint32_t*)&h6, *(uint32_t*)&h7 };
            *(uint4*)(smh + p * KH_AB + arow * 144 + akq * 2)      = s0;
            *(uint4*)(smh + p * KH_AB + arow * 144 + akq * 2 + 16) = s1;
        }
        if (cc < 7) {
#pragma unroll
            for (int g = 0; g < 4; g++) av4[g] = *(const float4*)(asrc + (cc + 1) * 64 + g * 4);
        }

        if (cc < 7) cp_wait1(); else cp_wait0();
        __syncthreads();

        if (cc + 2 < 8) {
            const int b32 = (cc + 2) - ((cc + 2) / 3) * 3;
            uint32_t bdst = B0 + (uint32_t)b32 * KH_BB;
            const __half* src = g_ham16T + (cc + 2) * 64;
#pragma unroll
            for (int q = 0; q < 4; q++) {
                int idx = q * 256 + tid;
                int c = idx >> 3, f8 = idx & 7;
                cp16(bdst + (uint32_t)(c * 144 + f8 * 16), src + c * IN_F + f8 * 8);
            }
            cp_commit();
        }

        {
            const uint32_t pa = sb + (uint32_t)p * KH_AB + aoffr;
            const uint32_t pb = B0 + (uint32_t)b3 * KH_BB + boffr;
#pragma unroll
            for (int ks = 0; ks < 4; ks++) {
                uint32_t a0[4], a1[4], b01[4], b23[4];
                ldsm4(a0, pa + ks * 32);
                ldsm4(a1, pa + ks * 32 + 16 * 144);
                ldsm4(b01, pb + ks * 32);
                ldsm4(b23, pb + ks * 32 + 16 * 144);
                mma16(acc[0][0], a0, b01 + 0);
                mma16(acc[0][1], a0, b01 + 2);
                mma16(acc[0][2], a0, b23 + 0);
                mma16(acc[0][3], a0, b23 + 2);
                mma16(acc[1][0], a1, b01 + 0);
                mma16(acc[1][1], a1, b01 + 2);
                mma16(acc[1][2], a1, b23 + 0);
                mma16(acc[1][3], a1, b23 + 2);
            }
        }
    }
    __syncthreads();

    float* C = (float*)smh;                // 64 x 132 floats = 33792 B
#pragma unroll
    for (int mb = 0; mb < 2; mb++) {
        int r0 = m0 + mb * 16 + gid;
#pragma unroll
        for (int nb = 0; nb < 4; nb++) {
            int col = n0 + nb * 8 + t4 * 2;
            *(float2*)(C + r0 * 132 + col)       = make_float2(acc[mb][nb][0], acc[mb][nb][1]);
            *(float2*)(C + (r0 + 8) * 132 + col) = make_float2(acc[mb][nb][2], acc[mb][nb][3]);
        }
    }
    __syncthreads();

    {
        int r = tid >> 2, cq = (tid & 3) * 32;
#pragma unroll
        for (int q = 0; q < 8; q++) {
            float4 v = *(float4*)(C + r * 132 + cq + q * 4);
            *(float4*)(g_h + (size_t)(i0 + r) * OUT_F + cq + q * 4) = v;
        }
    }
    {
        int c = tid >> 1, j0 = (tid & 1) * 32;
        uint32_t hw[16];
#pragma unroll
        for (int q = 0; q < 16; q++) {
            float f0 = C[(j0 + 2 * q) * 132 + c];
            float f1 = C[(j0 + 2 * q + 1) * 132 + c];
            __half2 h = __floats2half2_rn(f0, f1);
            hw[q] = *(uint32_t*)&h;
        }
        uint4* dst = (uint4*)(g_hT16 + (size_t)c * N_NODES + i0 + j0);
#pragma unroll
        for (int q = 0; q < 4; q++)
            dst[q] = make_uint4(hw[q * 4], hw[q * 4 + 1], hw[q * 4 + 2], hw[q * 4 + 3]);
    }
    {
        float a1v[4], a2v[4];
#pragma unroll
        for (int q = 0; q < 4; q++) {
            a1v[q] = a_vec[lane + q * 32];
            a2v[q] = a_vec[OUT_F + lane + q * 32];
        }
        float m2 = -1e30f;
#pragma unroll
        for (int rr = 0; rr < 8; rr++) {
            int r = wid * 8 + rr;
            float s1 = 0.f, s2 = 0.f;
#pragma unroll
            for (int q = 0; q < 4; q++) {
                float hv = C[r * 132 + lane + q * 32];
                s1 = fmaf(hv, a1v[q], s1);
                s2 = fmaf(hv, a2v[q], s2);
            }
#pragma unroll
            for (int off = 16; off > 0; off >>= 1) {
                s1 += __shfl_xor_sync(0xffffffffu, s1, off);
                s2 += __shfl_xor_sync(0xffffffffu, s2, off);
            }
            if (lane == 0) {
                g_s1[i0 + r] = s1;
                g_s2[i0 + r] = s2;
                m2 = fmaxf(m2, s2);
            }
        }
        if (lane == 0) {
            uint32_t u = __float_as_uint(m2);
            u = (u & 0x80000000u) ? ~u : (u | 0x80000000u);
            atomicMax(&g_s2max_u, u);
        }
    }
}

// ---------------- K2: per-node exp factors (rescaled so all <= 1), + zero BN sums ----------------
__global__ void k_prep() {
    int i = blockIdx.x * blockDim.x + threadIdx.x;
    if (blockIdx.x == 0 && threadIdx.x < 128) {
        g_colsum[threadIdx.x] = 0.f; g_colsumsq[threadIdx.x] = 0.f;
    }
    uint32_t mu = g_s2max_u;
    float s2max = (mu & 0x80000000u) ? __uint_as_float(mu ^ 0x80000000u)
                                     : __uint_as_float(~mu);
    float s1 = g_s1[i], s2 = g_s2[i];
    float t = s1 + s2max;
    float m = (t > 0.f) ? t : ALPHA * t;
    float A1 = __expf(s1 + s2max - m);
    float A2 = __expf(ALPHA * (s1 + s2max) - m);
    float E1 = __expf(s2 - s2max);
    float E2 = __expf(ALPHA * (s2 - s2max));
    g_A12[i] = make_float2(A1, A2);
    __half2 e = __floats2half2_rn(E1, E2);
    g_E12h[i] = *(uint32_t*)&e;
}

// ---------------- K3: fused attention (R14 proven version, byte-for-byte) ----------------
// 256 CTAs (128 rowblocks x 2 j-halves) x 256 thr. BM=64, BN=128, BK=64, 64 chunks.
#define PT_B 9216                         // 64 rows * 144 B
#define HS_B 18432                        // 128 rows * 144 B
#define H_OFF (2 * PT_B)                  // 18432
#define Z_OFF (H_OFF + 3 * HS_B)          // 73728
#define ATTN_SMEM (Z_OFF + 256)           // 73984
__global__ void __launch_bounds__(256, 2) k_attn(const int* __restrict__ adj) {
    extern __shared__ __align__(16) char smem[];
    const uint32_t sb = smem_u32(smem);
    float* zsh = (float*)(smem + Z_OFF);

    const int tid  = threadIdx.x;
    const int wid  = tid >> 5;
    const int lane = tid & 31;
    const int gid  = lane >> 2;
    const int t4   = lane & 3;
    const int bid  = blockIdx.x;
    const int i0   = (bid >> 1) * 64;
    const int jb0  = (bid & 1) * 4096;
    const int m0   = (wid >> 2) * 32;
    const int n0   = (wid & 3) * 32;

    if (tid < 64) zsh[tid] = 0.f;

    const int prow = tid >> 2;
    const int jl0  = (tid & 3) * 16;
    const float2 a12 = g_A12[i0 + prow];
    const float A1 = a12.x, A2 = a12.y;
    const int* arow = adj + (size_t)(i0 + prow) * N_NODES + jb0 + jl0;
    const uint32_t* esrc = g_E12h + jb0 + jl0;

    const uint32_t aoffr = (uint32_t)((m0 + (lane & 7) + ((lane >> 3) & 1) * 8) * 144
                                      + ((lane >> 4) & 1) * 16);
    const uint32_t boffr = (uint32_t)((n0 + (lane & 7) + ((lane >> 4) & 1) * 8) * 144
                                      + ((lane >> 3) & 1) * 16);

    float acc[2][4][4];
#pragma unroll
    for (int mb = 0; mb < 2; mb++)
#pragma unroll
        for (int nb = 0; nb < 4; nb++)
#pragma unroll
            for (int q = 0; q < 4; q++) acc[mb][nb][q] = 0.f;
    float zacc = 0.f;

    // ---- prologue: stage H(0), H(1); prefetch adj/E(0) into regs ----
#pragma unroll
    for (int s = 0; s < 2; s++) {
        uint32_t hdst = sb + H_OFF + (uint32_t)s * HS_B;
        const __half* src = g_hT16 + jb0 + s * 64;
#pragma unroll
        for (int q = 0; q < 4; q++) {
            int idx = q * 256 + tid;
            int c = idx >> 3, f8 = idx & 7;
            cp16(hdst + (uint32_t)(c * 144 + f8 * 16),
                 src + (size_t)c * N_NODES + f8 * 8);
        }
        cp_commit();
    }
    int4 av[4];
    uint4 ew[4];
#pragma unroll
    for (int g = 0; g < 4; g++) av[g] = *(const int4*)(arow + g * 4);
#pragma unroll
    for (int g = 0; g < 4; g++) ew[g] = *(const uint4*)(esrc + g * 4);

    for (int cc = 0; cc < 64; cc++) {
        const int p = cc & 1;
        const int hb = cc - (cc / 3) * 3;      // cc % 3

        // ---- build P(cc) from registers (16 j's per thread) ----
        {
            char* PtB = smem + p * PT_B;
#pragma unroll
            for (int g = 0; g < 4; g++) {
                int4 a = av[g];
                float2 f0 = __half22float2(*(__half2*)&ew[g].x);
                float2 f1 = __half22float2(*(__half2*)&ew[g].y);
                float2 f2 = __half22float2(*(__half2*)&ew[g].z);
                float2 f3 = __half22float2(*(__half2*)&ew[g].w);
                float q0 = fmaxf(A1 * f0.x, A2 * f0.y);
                float q1 = fmaxf(A1 * f1.x, A2 * f1.y);
                float q2 = fmaxf(A1 * f2.x, A2 * f2.y);
                float q3 = fmaxf(A1 * f3.x, A2 * f3.y);
                if (a.x <= 0) q0 = 0.f;
                if (a.y <= 0) q1 = 0.f;
                if (a.z <= 0) q2 = 0.f;
                if (a.w <= 0) q3 = 0.f;
                __half2 h20 = __floats2half2_rn(q0, q1);
                __half2 h21 = __floats2half2_rn(q2, q3);
                float2 r0 = __half22float2(h20);
                float2 r1 = __half22float2(h21);
                zacc += (r0.x + r0.y) + (r1.x + r1.y);
                uint2 st = { *(uint32_t*)&h20, *(uint32_t*)&h21 };
                *(uint2*)(PtB + prow * 144 + (jl0 + g * 4) * 2) = st;
            }
        }

        // ---- prefetch adj/E for cc+1 (in flight across MMA) ----
        if (cc < 63) {
            const int nj = (cc + 1) * 64;
#pragma unroll
            for (int g = 0; g < 4; g++) av[g] = *(const int4*)(arow + nj + g * 4);
#pragma unroll
            for (int g = 0; g < 4; g++) ew[g] = *(const uint4*)(esrc + nj + g * 4);
        }

        if (cc < 62) cp_wait1(); else cp_wait0();
        __syncthreads();     // P(cc) visible; H(cc) resident; MMA(cc-1) complete

        // ---- stage H(cc+2) ----
        if (cc + 2 < 64) {
            const int hb2 = (cc + 2) - ((cc + 2) / 3) * 3;
            uint32_t hdst = sb + H_OFF + (uint32_t)hb2 * HS_B;
            const __half* src = g_hT16 + jb0 + (cc + 2) * 64;
#pragma unroll
            for (int q = 0; q < 4; q++) {
                int idx = q * 256 + tid;
                int c = idx >> 3, f8 = idx & 7;
                cp16(hdst + (uint32_t)(c * 144 + f8 * 16),
                     src + (size_t)c * N_NODES + f8 * 8);
            }
            cp_commit();
        }

        // ---- MMA(cc): A from Pbuf[p], B from Hbuf[hb] ----
        {
            const uint32_t pa = sb + (uint32_t)p * PT_B + aoffr;
            const uint32_t pb = sb + H_OFF + (uint32_t)hb * HS_B + boffr;
#pragma unroll
            for (int ks = 0; ks < 4; ks++) {
                uint32_t a0[4], a1[4], b01[4], b23[4];
                ldsm4(a0, pa + ks * 32);
                ldsm4(a1, pa + ks * 32 + 16 * 144);
                ldsm4(b01, pb + ks * 32);
                ldsm4(b23, pb + ks * 32 + 16 * 144);
                mma16(acc[0][0], a0, b01 + 0);
                mma16(acc[0][1], a0, b01 + 2);
                mma16(acc[0][2], a0, b23 + 0);
                mma16(acc[0][3], a0, b23 + 2);
                mma16(acc[1][0], a1, b01 + 0);
                mma16(acc[1][1], a1, b01 + 2);
                mma16(acc[1][2], a1, b23 + 0);
                mma16(acc[1][3], a1, b23 + 2);
            }
        }
    }

    // ---- epilogue: write UNnormalized partials + z ----
    atomicAdd(&zsh[prow], zacc);
    __syncthreads();
    float* hpD = (bid & 1) ? g_hp1 : g_hp0;
    float* zD  = (bid & 1) ? g_z1  : g_z0;
    if (tid < 64) zD[i0 + tid] = zsh[tid];
#pragma unroll
    for (int mb = 0; mb < 2; mb++) {
        int r0 = m0 + mb * 16 + gid;
#pragma unroll
        for (int nb = 0; nb < 4; nb++) {
            int col = n0 + nb * 8 + t4 * 2;
            float2 v0 = {acc[mb][nb][0], acc[mb][nb][1]};
            float2 v1 = {acc[mb][nb][2], acc[mb][nb][3]};
            *(float2*)(hpD + (size_t)(i0 + r0) * OUT_F + col)     = v0;
            *(float2*)(hpD + (size_t)(i0 + r0 + 8) * OUT_F + col) = v1;
        }
    }
}

// ---------------- K4: BN column stats directly from partials (float4) ----------------
__global__ void k_stats() {
    int tid = threadIdx.x;
    int col = (tid & 31) * 4;
    int rsub = tid >> 5;                   // 0..7
    int r0 = blockIdx.x * 64;              // 128 blocks x 64 rows
    float4 s = {0.f, 0.f, 0.f, 0.f};
    float4 q = {0.f, 0.f, 0.f, 0.f};
#pragma unroll
    for (int it = 0; it < 8; it++) {
        int row = r0 + rsub + it * 8;
        size_t idx = (size_t)row * OUT_F + col;
        float4 a = *(const float4*)(g_hp0 + idx);
        float4 b = *(const float4*)(g_hp1 + idx);
        float invz = 1.0f / (g_z0[row] + g_z1[row]);
        float m0 = (a.x + b.x) * invz;
        float m1 = (a.y + b.y) * invz;
        float m2 = (a.z + b.z) * invz;
        float m3 = (a.w + b.w) * invz;
        s.x += m0; s.y += m1; s.z += m2; s.w += m3;
        q.x = fmaf(m0, m0, q.x); q.y = fmaf(m1, m1, q.y);
        q.z = fmaf(m2, m2, q.z); q.w = fmaf(m3, m3, q.w);
    }
    atomicAdd(&g_colsum[col],     s.x);
    atomicAdd(&g_colsum[col + 1], s.y);
    atomicAdd(&g_colsum[col + 2], s.z);
    atomicAdd(&g_colsum[col + 3], s.w);
    atomicAdd(&g_colsumsq[col],     q.x);
    atomicAdd(&g_colsumsq[col + 1], q.y);
    atomicAdd(&g_colsumsq[col + 2], q.z);
    atomicAdd(&g_colsumsq[col + 3], q.w);
}

// ---------------- K5: merge + normalize + BatchNorm + ELU (float4) ----------------
__global__ void k_bn(const float* __restrict__ gamma, const float* __restrict__ beta,
                     float* __restrict__ out) {
    int t = blockIdx.x * blockDim.x + threadIdx.x;    // 0..262143
    int base = t * 4;
    int col = base & 127;
    int row = base >> 7;
    const float invN = 1.0f / (float)N_NODES;
    float4 cs = *(const float4*)(g_colsum + col);
    float4 cq = *(const float4*)(g_colsumsq + col);
    float4 gm = *(const float4*)(gamma + col);
    float4 bt = *(const float4*)(beta + col);
    float4 a = *(const float4*)(g_hp0 + base);
    float4 b = *(const float4*)(g_hp1 + base);
    float invz = 1.0f / (g_z0[row] + g_z1[row]);
    float4 o;
    {
        float mean = cs.x * invN;
        float var  = cq.x * invN - mean * mean;
        float v = ((a.x + b.x) * invz - mean) * rsqrtf(var + BN_EPS) * gm.x + bt.x;
        o.x = (v > 0.f) ? v : expm1f(v);
    }
    {
        float mean = cs.y * invN;
        float var  = cq.y * invN - mean * mean;
        float v = ((a.y + b.y) * invz - mean) * rsqrtf(var + BN_EPS) * gm.y + bt.y;
        o.y = (v > 0.f) ? v : expm1f(v);
    }
    {
        float mean = cs.z * invN;
        float var  = cq.z * invN - mean * mean;
        float v = ((a.z + b.z) * invz - mean) * rsqrtf(var + BN_EPS) * gm.z + bt.z;
        o.z = (v > 0.f) ? v : expm1f(v);
    }
    {
        float mean = cs.w * invN;
        float var  = cq.w * invN - mean * mean;
        float v = ((a.w + b.w) * invz - mean) * rsqrtf(var + BN_EPS) * gm.w + bt.w;
        o.w = (v > 0.f) ? v : expm1f(v);
    }
    *(float4*)(out + base) = o;
}

// ---------------- launch ----------------
extern "C" void kernel_launch(void* const* d_in, const int* in_sizes, int n_in,
                              void* d_out, int out_size) {
    (void)in_sizes; (void)n_in; (void)out_size;
    const float* inp   = (const float*)d_in[0];
    const int*   adj   = (const int*)  d_in[1];
    const float* W     = (const float*)d_in[2];
    const float* a_vec = (const float*)d_in[3];
    const float* gamma = (const float*)d_in[4];
    const float* beta  = (const float*)d_in[5];
    float* out = (float*)d_out;

    static int smem_set = 0;
    if (!smem_set) {
        cudaFuncSetAttribute(k_attn, cudaFuncAttributeMaxDynamicSharedMemorySize, ATTN_SMEM);
        cudaFuncSetAttribute(k_h,    cudaFuncAttributeMaxDynamicSharedMemorySize, KH_SMEM);
        smem_set = 1;
    }

    k_ham16<<<256, 256>>>(W);
    k_h    <<<128, 256, KH_SMEM>>>(inp, a_vec);
    k_prep <<<32, 256>>>();
    k_attn <<<256, 256, ATTN_SMEM>>>(adj);     // launch #4 -> ncu captures this
    k_stats<<<128, 256>>>();
    k_bn   <<<1024, 256>>>(gamma, beta, out);
}

// round 17
// speedup vs baseline: 1.5697x; 1.2418x over previous
#include <cuda_runtime.h>
#include <cuda_fp16.h>
#include <cstdint>

#define N_NODES 8192
#define IN_F    512
#define OUT_F   128
#define ALPHA   0.2f
#define BN_EPS  1e-5f

// ---------------- scratch ----------------
__device__ __align__(16) __half g_ham16T[OUT_F * IN_F];      // [c][k] fp16, 128x512
__device__ __align__(16) float  g_h[N_NODES * OUT_F];        // fp32 (staging for s1/s2 path)
__device__ __align__(16) __half g_hT16[OUT_F * N_NODES];     // fp16 transposed [c][j]
__device__ __align__(16) float  g_hp0[N_NODES * OUT_F];      // partial, j-half 0
__device__ __align__(16) float  g_hp1[N_NODES * OUT_F];      // partial, j-half 1
__device__ float  g_z0[N_NODES];
__device__ float  g_z1[N_NODES];
__device__ float  g_s1[N_NODES];
__device__ float  g_s2[N_NODES];
__device__ unsigned int g_s2max_u = 0x007FFFFFu;             // encoded -inf (idempotent)
__device__ __align__(16) float2   g_A12[N_NODES];            // fp32 {A1, A2}
__device__ __align__(8)  uint32_t g_E12h[N_NODES];           // half2 {E1, E2}, both <= 1
__device__ float g_colsum[OUT_F];
__device__ float g_colsumsq[OUT_F];

// ---------------- helpers ----------------
__device__ __forceinline__ uint32_t smem_u32(const void* p) {
    uint32_t a;
    asm("{ .reg .u64 t; cvta.to.shared.u64 t, %1; cvt.u32.u64 %0, t; }" : "=r"(a) : "l"(p));
    return a;
}
__device__ __forceinline__ void cp16(uint32_t dst, const void* src) {
    asm volatile("cp.async.cg.shared.global [%0], [%1], 16;" :: "r"(dst), "l"(src) : "memory");
}
__device__ __forceinline__ void cp_commit() {
    asm volatile("cp.async.commit_group;" ::: "memory");
}
__device__ __forceinline__ void cp_wait0() {
    asm volatile("cp.async.wait_group 0;" ::: "memory");
}
__device__ __forceinline__ void cp_wait1() {
    asm volatile("cp.async.wait_group 1;" ::: "memory");
}
__device__ __forceinline__ void ldsm4(uint32_t* r, uint32_t addr) {
    asm volatile("ldmatrix.sync.aligned.m8n8.x4.shared.b16 {%0,%1,%2,%3}, [%4];"
                 : "=r"(r[0]), "=r"(r[1]), "=r"(r[2]), "=r"(r[3]) : "r"(addr));
}
__device__ __forceinline__ void mma16(float* c, const uint32_t* a, const uint32_t* b) {
    asm volatile(
        "mma.sync.aligned.m16n8k16.row.col.f32.f16.f16.f32 "
        "{%0,%1,%2,%3}, {%4,%5,%6,%7}, {%8,%9}, {%0,%1,%2,%3};"
        : "+f"(c[0]), "+f"(c[1]), "+f"(c[2]), "+f"(c[3])
        : "r"(a[0]), "r"(a[1]), "r"(a[2]), "r"(a[3]), "r"(b[0]), "r"(b[1]));
}
__device__ __forceinline__ float quat_sign(int rb, int cb) {
    float sgn = 1.f;
    if (cb == 0) { if (rb != 0) sgn = -1.f; }
    else if (rb == (cb % 3) + 1) sgn = -1.f;
    return sgn;
}

// ---------------- K0: transposed fp16 hamilton [c][k] ----------------
__global__ void k_ham16(const float* __restrict__ W) {
    int idx = blockIdx.x * blockDim.x + threadIdx.x;   // 0..65535
    int c = idx >> 9, k = idx & 511;
    int rb = k >> 7, rr = k & 127;
    int cb = c >> 5, cc = c & 31;
    int comp = rb ^ cb;
    g_ham16T[idx] = __float2half(quat_sign(rb, cb) * W[rr * 128 + comp * 32 + cc]);
}

// ---------------- K1: h = input @ hamilton via fp16 mma, pipelined ----------------
#define KH_AB 9216                         // 64 rows * 144 B
#define KH_BB 18432                        // 128 rows * 144 B
#define KH_SMEM (2 * KH_AB + 3 * KH_BB)    // 73728
__global__ void __launch_bounds__(256) k_h(const float* __restrict__ inp,
                                           const float* __restrict__ a_vec) {
    extern __shared__ __align__(16) char smh[];
    const uint32_t sb = smem_u32(smh);
    const uint32_t B0 = sb + 2 * KH_AB;

    const int tid  = threadIdx.x;
    const int wid  = tid >> 5;
    const int lane = tid & 31;
    const int gid  = lane >> 2;
    const int t4   = lane & 3;
    const int i0   = blockIdx.x * 64;
    const int m0   = (wid >> 2) * 32;
    const int n0   = (wid & 3) * 32;

    const uint32_t aoffr = (uint32_t)((m0 + (lane & 7) + ((lane >> 3) & 1) * 8) * 144
                                      + ((lane >> 4) & 1) * 16);
    const uint32_t boffr = (uint32_t)((n0 + (lane & 7) + ((lane >> 4) & 1) * 8) * 144
                                      + ((lane >> 3) & 1) * 16);

    const int arow = tid >> 2;            // 0..63
    const int akq  = (tid & 3) * 16;      // 0/16/32/48
    const float* asrc = inp + (size_t)(i0 + arow) * IN_F + akq;

    float acc[2][4][4];
#pragma unroll
    for (int mb = 0; mb < 2; mb++)
#pragma unroll
        for (int nb = 0; nb < 4; nb++)
#pragma unroll
            for (int q = 0; q < 4; q++) acc[mb][nb][q] = 0.f;

#pragma unroll
    for (int s = 0; s < 2; s++) {
        uint32_t bdst = B0 + (uint32_t)s * KH_BB;
        const __half* src = g_ham16T + s * 64;
#pragma unroll
        for (int q = 0; q < 4; q++) {
            int idx = q * 256 + tid;
            int c = idx >> 3, f8 = idx & 7;
            cp16(bdst + (uint32_t)(c * 144 + f8 * 16), src + c * IN_F + f8 * 8);
        }
        cp_commit();
    }
    float4 av4[4];
#pragma unroll
    for (int g = 0; g < 4; g++) av4[g] = *(const float4*)(asrc + g * 4);

    for (int cc = 0; cc < 8; cc++) {
        const int p = cc & 1;
        const int b3 = cc - (cc / 3) * 3;          // cc % 3

        {
            __half2 h0 = __floats2half2_rn(av4[0].x, av4[0].y);
            __half2 h1 = __floats2half2_rn(av4[0].z, av4[0].w);
            __half2 h2 = __floats2half2_rn(av4[1].x, av4[1].y);
            __half2 h3 = __floats2half2_rn(av4[1].z, av4[1].w);
            __half2 h4 = __floats2half2_rn(av4[2].x, av4[2].y);
            __half2 h5 = __floats2half2_rn(av4[2].z, av4[2].w);
            __half2 h6 = __floats2half2_rn(av4[3].x, av4[3].y);
            __half2 h7 = __floats2half2_rn(av4[3].z, av4[3].w);
            uint4 s0 = { *(uint32_t*)&h0, *(uint32_t*)&h1, *(uint32_t*)&h2, *(uint32_t*)&h3 };
            uint4 s1 = { *(uint32_t*)&h4, *(uint32_t*)&h5, *(uint32_t*)&h6, *(uint32_t*)&h7 };
            *(uint4*)(smh + p * KH_AB + arow * 144 + akq * 2)      = s0;
            *(uint4*)(smh + p * KH_AB + arow * 144 + akq * 2 + 16) = s1;
        }
        if (cc < 7) {
#pragma unroll
            for (int g = 0; g < 4; g++) av4[g] = *(const float4*)(asrc + (cc + 1) * 64 + g * 4);
        }

        if (cc < 7) cp_wait1(); else cp_wait0();
        __syncthreads();

        if (cc + 2 < 8) {
            const int b32 = (cc + 2) - ((cc + 2) / 3) * 3;
            uint32_t bdst = B0 + (uint32_t)b32 * KH_BB;
            const __half* src = g_ham16T + (cc + 2) * 64;
#pragma unroll
            for (int q = 0; q < 4; q++) {
                int idx = q * 256 + tid;
                int c = idx >> 3, f8 = idx & 7;
                cp16(bdst + (uint32_t)(c * 144 + f8 * 16), src + c * IN_F + f8 * 8);
            }
            cp_commit();
        }

        {
            const uint32_t pa = sb + (uint32_t)p * KH_AB + aoffr;
            const uint32_t pb = B0 + (uint32_t)b3 * KH_BB + boffr;
#pragma unroll
            for (int ks = 0; ks < 4; ks++) {
                uint32_t a0[4], a1[4], b01[4], b23[4];
                ldsm4(a0, pa + ks * 32);
                ldsm4(a1, pa + ks * 32 + 16 * 144);
                ldsm4(b01, pb + ks * 32);
                ldsm4(b23, pb + ks * 32 + 16 * 144);
                mma16(acc[0][0], a0, b01 + 0);
                mma16(acc[0][1], a0, b01 + 2);
                mma16(acc[0][2], a0, b23 + 0);
                mma16(acc[0][3], a0, b23 + 2);
                mma16(acc[1][0], a1, b01 + 0);
                mma16(acc[1][1], a1, b01 + 2);
                mma16(acc[1][2], a1, b23 + 0);
                mma16(acc[1][3], a1, b23 + 2);
            }
        }
    }
    __syncthreads();

    float* C = (float*)smh;                // 64 x 132 floats = 33792 B
#pragma unroll
    for (int mb = 0; mb < 2; mb++) {
        int r0 = m0 + mb * 16 + gid;
#pragma unroll
        for (int nb = 0; nb < 4; nb++) {
            int col = n0 + nb * 8 + t4 * 2;
            *(float2*)(C + r0 * 132 + col)       = make_float2(acc[mb][nb][0], acc[mb][nb][1]);
            *(float2*)(C + (r0 + 8) * 132 + col) = make_float2(acc[mb][nb][2], acc[mb][nb][3]);
        }
    }
    __syncthreads();

    {
        int r = tid >> 2, cq = (tid & 3) * 32;
#pragma unroll
        for (int q = 0; q < 8; q++) {
            float4 v = *(float4*)(C + r * 132 + cq + q * 4);
            *(float4*)(g_h + (size_t)(i0 + r) * OUT_F + cq + q * 4) = v;
        }
    }
    {
        int c = tid >> 1, j0 = (tid & 1) * 32;
        uint32_t hw[16];
#pragma unroll
        for (int q = 0; q < 16; q++) {
            float f0 = C[(j0 + 2 * q) * 132 + c];
            float f1 = C[(j0 + 2 * q + 1) * 132 + c];
            __half2 h = __floats2half2_rn(f0, f1);
            hw[q] = *(uint32_t*)&h;
        }
        uint4* dst = (uint4*)(g_hT16 + (size_t)c * N_NODES + i0 + j0);
#pragma unroll
        for (int q = 0; q < 4; q++)
            dst[q] = make_uint4(hw[q * 4], hw[q * 4 + 1], hw[q * 4 + 2], hw[q * 4 + 3]);
    }
    {
        float a1v[4], a2v[4];
#pragma unroll
        for (int q = 0; q < 4; q++) {
            a1v[q] = a_vec[lane + q * 32];
            a2v[q] = a_vec[OUT_F + lane + q * 32];
        }
        float m2 = -1e30f;
#pragma unroll
        for (int rr = 0; rr < 8; rr++) {
            int r = wid * 8 + rr;
            float s1 = 0.f, s2 = 0.f;
#pragma unroll
            for (int q = 0; q < 4; q++) {
                float hv = C[r * 132 + lane + q * 32];
                s1 = fmaf(hv, a1v[q], s1);
                s2 = fmaf(hv, a2v[q], s2);
            }
#pragma unroll
            for (int off = 16; off > 0; off >>= 1) {
                s1 += __shfl_xor_sync(0xffffffffu, s1, off);
                s2 += __shfl_xor_sync(0xffffffffu, s2, off);
            }
            if (lane == 0) {
                g_s1[i0 + r] = s1;
                g_s2[i0 + r] = s2;
                m2 = fmaxf(m2, s2);
            }
        }
        if (lane == 0) {
            uint32_t u = __float_as_uint(m2);
            u = (u & 0x80000000u) ? ~u : (u | 0x80000000u);
            atomicMax(&g_s2max_u, u);
        }
    }
}

// ---------------- K2: per-node exp factors (rescaled so all <= 1), + zero BN sums ----------------
__global__ void k_prep() {
    int i = blockIdx.x * blockDim.x + threadIdx.x;
    if (blockIdx.x == 0 && threadIdx.x < 128) {
        g_colsum[threadIdx.x] = 0.f; g_colsumsq[threadIdx.x] = 0.f;
    }
    uint32_t mu = g_s2max_u;
    float s2max = (mu & 0x80000000u) ? __uint_as_float(mu ^ 0x80000000u)
                                     : __uint_as_float(~mu);
    float s1 = g_s1[i], s2 = g_s2[i];
    float t = s1 + s2max;
    float m = (t > 0.f) ? t : ALPHA * t;
    float A1 = __expf(s1 + s2max - m);
    float A2 = __expf(ALPHA * (s1 + s2max) - m);
    float E1 = __expf(s2 - s2max);
    float E2 = __expf(ALPHA * (s2 - s2max));
    g_A12[i] = make_float2(A1, A2);
    __half2 e = __floats2half2_rn(E1, E2);
    g_E12h[i] = *(uint32_t*)&e;
}

// ---------------- K3: fused attention (R14 proven version, byte-for-byte) ----------------
// 256 CTAs (128 rowblocks x 2 j-halves) x 256 thr. BM=64, BN=128, BK=64, 64 chunks.
#define PT_B 9216                         // 64 rows * 144 B
#define HS_B 18432                        // 128 rows * 144 B
#define H_OFF (2 * PT_B)                  // 18432
#define Z_OFF (H_OFF + 3 * HS_B)          // 73728
#define ATTN_SMEM (Z_OFF + 256)           // 73984
__global__ void __launch_bounds__(256, 2) k_attn(const int* __restrict__ adj) {
    extern __shared__ __align__(16) char smem[];
    const uint32_t sb = smem_u32(smem);
    float* zsh = (float*)(smem + Z_OFF);

    const int tid  = threadIdx.x;
    const int wid  = tid >> 5;
    const int lane = tid & 31;
    const int gid  = lane >> 2;
    const int t4   = lane & 3;
    const int bid  = blockIdx.x;
    const int i0   = (bid >> 1) * 64;
    const int jb0  = (bid & 1) * 4096;
    const int m0   = (wid >> 2) * 32;
    const int n0   = (wid & 3) * 32;

    if (tid < 64) zsh[tid] = 0.f;

    const int prow = tid >> 2;
    const int jl0  = (tid & 3) * 16;
    const float2 a12 = g_A12[i0 + prow];
    const float A1 = a12.x, A2 = a12.y;
    const int* arow = adj + (size_t)(i0 + prow) * N_NODES + jb0 + jl0;
    const uint32_t* esrc = g_E12h + jb0 + jl0;

    const uint32_t aoffr = (uint32_t)((m0 + (lane & 7) + ((lane >> 3) & 1) * 8) * 144
                                      + ((lane >> 4) & 1) * 16);
    const uint32_t boffr = (uint32_t)((n0 + (lane & 7) + ((lane >> 4) & 1) * 8) * 144
                                      + ((lane >> 3) & 1) * 16);

    float acc[2][4][4];
#pragma unroll
    for (int mb = 0; mb < 2; mb++)
#pragma unroll
        for (int nb = 0; nb < 4; nb++)
#pragma unroll
            for (int q = 0; q < 4; q++) acc[mb][nb][q] = 0.f;
    float zacc = 0.f;

    // ---- prologue: stage H(0), H(1); prefetch adj/E(0) into regs ----
#pragma unroll
    for (int s = 0; s < 2; s++) {
        uint32_t hdst = sb + H_OFF + (uint32_t)s * HS_B;
        const __half* src = g_hT16 + jb0 + s * 64;
#pragma unroll
        for (int q = 0; q < 4; q++) {
            int idx = q * 256 + tid;
            int c = idx >> 3, f8 = idx & 7;
            cp16(hdst + (uint32_t)(c * 144 + f8 * 16),
                 src + (size_t)c * N_NODES + f8 * 8);
        }
        cp_commit();
    }
    int4 av[4];
    uint4 ew[4];
#pragma unroll
    for (int g = 0; g < 4; g++) av[g] = *(const int4*)(arow + g * 4);
#pragma unroll
    for (int g = 0; g < 4; g++) ew[g] = *(const uint4*)(esrc + g * 4);

    for (int cc = 0; cc < 64; cc++) {
        const int p = cc & 1;
        const int hb = cc - (cc / 3) * 3;      // cc % 3

        // ---- build P(cc) from registers (16 j's per thread) ----
        {
            char* PtB = smem + p * PT_B;
#pragma unroll
            for (int g = 0; g < 4; g++) {
                int4 a = av[g];
                float2 f0 = __half22float2(*(__half2*)&ew[g].x);
                float2 f1 = __half22float2(*(__half2*)&ew[g].y);
                float2 f2 = __half22float2(*(__half2*)&ew[g].z);
                float2 f3 = __half22float2(*(__half2*)&ew[g].w);
                float q0 = fmaxf(A1 * f0.x, A2 * f0.y);
                float q1 = fmaxf(A1 * f1.x, A2 * f1.y);
                float q2 = fmaxf(A1 * f2.x, A2 * f2.y);
                float q3 = fmaxf(A1 * f3.x, A2 * f3.y);
                if (a.x <= 0) q0 = 0.f;
                if (a.y <= 0) q1 = 0.f;
                if (a.z <= 0) q2 = 0.f;
                if (a.w <= 0) q3 = 0.f;
                __half2 h20 = __floats2half2_rn(q0, q1);
                __half2 h21 = __floats2half2_rn(q2, q3);
                float2 r0 = __half22float2(h20);
                float2 r1 = __half22float2(h21);
                zacc += (r0.x + r0.y) + (r1.x + r1.y);
                uint2 st = { *(uint32_t*)&h20, *(uint32_t*)&h21 };
                *(uint2*)(PtB + prow * 144 + (jl0 + g * 4) * 2) = st;
            }
        }

        // ---- prefetch adj/E for cc+1 (in flight across MMA) ----
        if (cc < 63) {
            const int nj = (cc + 1) * 64;
#pragma unroll
            for (int g = 0; g < 4; g++) av[g] = *(const int4*)(arow + nj + g * 4);
#pragma unroll
            for (int g = 0; g < 4; g++) ew[g] = *(const uint4*)(esrc + nj + g * 4);
        }

        if (cc < 62) cp_wait1(); else cp_wait0();
        __syncthreads();     // P(cc) visible; H(cc) resident; MMA(cc-1) complete

        // ---- stage H(cc+2) ----
        if (cc + 2 < 64) {
            const int hb2 = (cc + 2) - ((cc + 2) / 3) * 3;
            uint32_t hdst = sb + H_OFF + (uint32_t)hb2 * HS_B;
            const __half* src = g_hT16 + jb0 + (cc + 2) * 64;
#pragma unroll
            for (int q = 0; q < 4; q++) {
                int idx = q * 256 + tid;
                int c = idx >> 3, f8 = idx & 7;
                cp16(hdst + (uint32_t)(c * 144 + f8 * 16),
                     src + (size_t)c * N_NODES + f8 * 8);
            }
            cp_commit();
        }

        // ---- MMA(cc): A from Pbuf[p], B from Hbuf[hb] ----
        {
            const uint32_t pa = sb + (uint32_t)p * PT_B + aoffr;
            const uint32_t pb = sb + H_OFF + (uint32_t)hb * HS_B + boffr;
#pragma unroll
            for (int ks = 0; ks < 4; ks++) {
                uint32_t a0[4], a1[4], b01[4], b23[4];
                ldsm4(a0, pa + ks * 32);
                ldsm4(a1, pa + ks * 32 + 16 * 144);
                ldsm4(b01, pb + ks * 32);
                ldsm4(b23, pb + ks * 32 + 16 * 144);
                mma16(acc[0][0], a0, b01 + 0);
                mma16(acc[0][1], a0, b01 + 2);
                mma16(acc[0][2], a0, b23 + 0);
                mma16(acc[0][3], a0, b23 + 2);
                mma16(acc[1][0], a1, b01 + 0);
                mma16(acc[1][1], a1, b01 + 2);
                mma16(acc[1][2], a1, b23 + 0);
                mma16(acc[1][3], a1, b23 + 2);
            }
        }
    }

    // ---- epilogue: write UNnormalized partials + z ----
    atomicAdd(&zsh[prow], zacc);
    __syncthreads();
    float* hpD = (bid & 1) ? g_hp1 : g_hp0;
    float* zD  = (bid & 1) ? g_z1  : g_z0;
    if (tid < 64) zD[i0 + tid] = zsh[tid];
#pragma unroll
    for (int mb = 0; mb < 2; mb++) {
        int r0 = m0 + mb * 16 + gid;
#pragma unroll
        for (int nb = 0; nb < 4; nb++) {
            int col = n0 + nb * 8 + t4 * 2;
            float2 v0 = {acc[mb][nb][0], acc[mb][nb][1]};
            float2 v1 = {acc[mb][nb][2], acc[mb][nb][3]};
            *(float2*)(hpD + (size_t)(i0 + r0) * OUT_F + col)     = v0;
            *(float2*)(hpD + (size_t)(i0 + r0 + 8) * OUT_F + col) = v1;
        }
    }
}

// ---------------- K4: BN column stats (R14 shape + smem reduction, 1 atomic/col/block) ----------------
__global__ void k_stats() {
    __shared__ float reds[128], redq[128];
    int col = threadIdx.x & 127;
    int h = threadIdx.x >> 7;
    int r0 = blockIdx.x * 32;
    float s = 0.f, q = 0.f;
    for (int r = h; r < 32; r += 2) {
        int row = r0 + r;
        size_t idx = (size_t)row * OUT_F + col;
        float z = g_z0[row] + g_z1[row];
        float m = (g_hp0[idx] + g_hp1[idx]) / z;
        s += m; q = fmaf(m, m, q);
    }
    if (h == 1) { reds[col] = s; redq[col] = q; }
    __syncthreads();
    if (h == 0) {
        atomicAdd(&g_colsum[col],   s + reds[col]);
        atomicAdd(&g_colsumsq[col], q + redq[col]);
    }
}

// ---------------- K5: merge + normalize + BatchNorm + ELU (float4) ----------------
__global__ void k_bn(const float* __restrict__ gamma, const float* __restrict__ beta,
                     float* __restrict__ out) {
    int t = blockIdx.x * blockDim.x + threadIdx.x;    // 0..262143
    int base = t * 4;
    int col = base & 127;
    int row = base >> 7;
    const float invN = 1.0f / (float)N_NODES;
    float4 cs = *(const float4*)(g_colsum + col);
    float4 cq = *(const float4*)(g_colsumsq + col);
    float4 gm = *(const float4*)(gamma + col);
    float4 bt = *(const float4*)(beta + col);
    float4 a = *(const float4*)(g_hp0 + base);
    float4 b = *(const float4*)(g_hp1 + base);
    float invz = 1.0f / (g_z0[row] + g_z1[row]);
    float4 o;
    {
        float mean = cs.x * invN;
        float var  = cq.x * invN - mean * mean;
        float v = ((a.x + b.x) * invz - mean) * rsqrtf(var + BN_EPS) * gm.x + bt.x;
        o.x = (v > 0.f) ? v : expm1f(v);
    }
    {
        float mean = cs.y * invN;
        float var  = cq.y * invN - mean * mean;
        float v = ((a.y + b.y) * invz - mean) * rsqrtf(var + BN_EPS) * gm.y + bt.y;
        o.y = (v > 0.f) ? v : expm1f(v);
    }
    {
        float mean = cs.z * invN;
        float var  = cq.z * invN - mean * mean;
        float v = ((a.z + b.z) * invz - mean) * rsqrtf(var + BN_EPS) * gm.z + bt.z;
        o.z = (v > 0.f) ? v : expm1f(v);
    }
    {
        float mean = cs.w * invN;
        float var  = cq.w * invN - mean * mean;
        float v = ((a.w + b.w) * invz - mean) * rsqrtf(var + BN_EPS) * gm.w + bt.w;
        o.w = (v > 0.f) ? v : expm1f(v);
    }
    *(float4*)(out + base) = o;
}

// ---------------- launch ----------------
extern "C" void kernel_launch(void* const* d_in, const int* in_sizes, int n_in,
                              void* d_out, int out_size) {
    (void)in_sizes; (void)n_in; (void)out_size;
    const float* inp   = (const float*)d_in[0];
    const int*   adj   = (const int*)  d_in[1];
    const float* W     = (const float*)d_in[2];
    const float* a_vec = (const float*)d_in[3];
    const float* gamma = (const float*)d_in[4];
    const float* beta  = (const float*)d_in[5];
    float* out = (float*)d_out;

    static int smem_set = 0;
    if (!smem_set) {
        cudaFuncSetAttribute(k_attn, cudaFuncAttributeMaxDynamicSharedMemorySize, ATTN_SMEM);
        cudaFuncSetAttribute(k_h,    cudaFuncAttributeMaxDynamicSharedMemorySize, KH_SMEM);
        smem_set = 1;
    }

    k_ham16<<<256, 256>>>(W);
    k_h    <<<128, 256, KH_SMEM>>>(inp, a_vec);
    k_prep <<<32, 256>>>();
    k_attn <<<256, 256, ATTN_SMEM>>>(adj);     // launch #4 -> ncu captures this
    k_stats<<<256, 256>>>();
    k_bn   <<<1024, 256>>>(gamma, beta, out);
}